// round 8
// baseline (speedup 1.0000x reference)
#include <cuda_runtime.h>
#include <math.h>

#define Nn 50000
#define Ee 800000
#define Ff 64
#define Tt 3
#define NSs 64
#define NTOT (4*Nn)
#define SCAN_TILE 4096
#define SCAN_BLOCKS ((Nn + SCAN_TILE - 1) / SCAN_TILE)   // 13

// ---------------- scratch (device globals; no allocation allowed) ----------------
__device__ __align__(16) float g_diff[Nn*192];   // per node: 3 normalized-difference rows
__device__ int g_soutdeg[Nn];
__device__ int g_sfill[Nn];
__device__ int g_soff[Nn+1];
__device__ int g_sdst[Ee];                        // src-CSR: destination per edge
__device__ int g_indeg[Nn];
__device__ int g_cnt3[Nn];                        // c1|c2<<10|c3<<20
__device__ int g_fill[Nn];
__device__ int g_off[Nn+1];
__device__ int g_eid[Ee];                         // dst-CSR: src | (mask<<16)
__device__ int g_bsumS[SCAN_BLOCKS];
__device__ int g_bsumD[SCAN_BLOCKS];
__device__ float g_dinv[4*Nn];
__device__ __align__(16) float g_xw0[Nn*Ff];
__device__ __align__(16) float g_h1[NTOT*Ff];
__device__ __align__(16) float g_xw1[NTOT*Ff];
__device__ __align__(16) float g_x2[Nn*Ff];       // replica-0 rows only
__device__ int g_cls[NTOT];
__device__ __align__(16) float g_hyper[NSs*Ff];
__device__ float g_colsum[NSs];

// ---------------- register-blocked GEMM: out = (relu?)X @ W (+bias), K=N=64 ----------------
// mode 0: plain. mode 1: diff rows + global init. mode 2: plain + fused dinv.
__global__ __launch_bounds__(128)
void gemm_rb(const float* __restrict__ X, const float* __restrict__ W,
             const float* __restrict__ bias, float* __restrict__ out,
             int rows, int relu_in, int mode)
{
    __shared__ float As[128*64];   // 32KB
    __shared__ float Bs[64*64];    // 16KB
    const int tid = threadIdx.x;
    const int tx = tid & 7;
    const int ty = tid >> 3;
    const int b  = blockIdx.y;
    const int row0 = blockIdx.x * 128;

    if (mode == 1 && b == 0) {
        int gi = blockIdx.x * 128 + tid;
        if (gi < Nn) {
            g_soutdeg[gi] = 0; g_sfill[gi] = 0;
            g_indeg[gi] = 0; g_cnt3[gi] = 0; g_fill[gi] = 0;
        }
        if (blockIdx.x == 0) {
            for (int i = tid; i < NSs*Ff; i += 128) g_hyper[i] = 0.0f;
            if (tid < NSs) g_colsum[tid] = (float)Nn;
        }
    }
    if (mode == 2 && b == 0) {
        int gi = blockIdx.x * 128 + tid;
        if (gi < Nn) {
            int dg = g_indeg[gi];
            int pk = g_cnt3[gi];
            g_dinv[gi]        = rsqrtf((float)dg + 1.0f);
            g_dinv[Nn + gi]   = rsqrtf((float)(pk & 1023) + 2.0f);
            g_dinv[2*Nn + gi] = rsqrtf((float)((pk >> 10) & 1023) + 2.0f);
            g_dinv[3*Nn + gi] = rsqrtf((float)((pk >> 20) & 1023) + 2.0f);
        }
    }

    const float* Wb = W + (size_t)b * 4096;

#pragma unroll
    for (int it = 0; it < 16; it++) {
        int idx = tid + it * 128;
        int r = idx >> 4, c4 = (idx & 15) << 2;
        int gr = row0 + r;
        float4 v = make_float4(0.f, 0.f, 0.f, 0.f);
        if (gr < rows) v = *(const float4*)&X[(size_t)gr*64 + c4];
        if (relu_in) { v.x = fmaxf(v.x,0.f); v.y = fmaxf(v.y,0.f); v.z = fmaxf(v.z,0.f); v.w = fmaxf(v.w,0.f); }
        *(float4*)&As[r*64 + c4] = v;
    }
#pragma unroll
    for (int it = 0; it < 8; it++) {
        int idx = tid + it * 128;
        int k = idx >> 4, c4 = (idx & 15) << 2;
        *(float4*)&Bs[k*64 + c4] = *(const float4*)&Wb[k*64 + c4];
    }
    __syncthreads();

    float acc[8][8];
#pragma unroll
    for (int i = 0; i < 8; i++)
#pragma unroll
        for (int j = 0; j < 8; j++) acc[i][j] = 0.f;

    const int rbase = ty * 8;
    const int c0 = tx * 8;
#pragma unroll
    for (int k0 = 0; k0 < 64; k0 += 4) {
        float4 a[8];
#pragma unroll
        for (int i = 0; i < 8; i++) a[i] = *(const float4*)&As[(rbase+i)*64 + k0];
#pragma unroll
        for (int kk = 0; kk < 4; kk++) {
            float4 b0 = *(const float4*)&Bs[(k0+kk)*64 + c0];
            float4 b1 = *(const float4*)&Bs[(k0+kk)*64 + c0 + 4];
            float bb[8] = {b0.x,b0.y,b0.z,b0.w,b1.x,b1.y,b1.z,b1.w};
#pragma unroll
            for (int i = 0; i < 8; i++) {
                float av = (kk==0) ? a[i].x : (kk==1) ? a[i].y : (kk==2) ? a[i].z : a[i].w;
#pragma unroll
                for (int j = 0; j < 8; j++) acc[i][j] += av * bb[j];
            }
        }
    }

    float bj[8];
#pragma unroll
    for (int j = 0; j < 8; j++) bj[j] = bias ? bias[(size_t)b*64 + c0 + j] : 0.f;

    if (mode != 1) {
        float* outb = out + (size_t)b * rows * 64;
#pragma unroll
        for (int i = 0; i < 8; i++) {
            int gr = row0 + rbase + i;
            if (gr >= rows) continue;
            float v[8];
#pragma unroll
            for (int j = 0; j < 8; j++) v[j] = acc[i][j] + bj[j];
            *(float4*)&outb[(size_t)gr*64 + c0]     = make_float4(v[0],v[1],v[2],v[3]);
            *(float4*)&outb[(size_t)gr*64 + c0 + 4] = make_float4(v[4],v[5],v[6],v[7]);
        }
    } else {
#pragma unroll
        for (int i = 0; i < 8; i++) {
            int gr = row0 + rbase + i;
            float v[8], x[8];
            float sqv = 0.f, sqx = 0.f;
#pragma unroll
            for (int j = 0; j < 8; j++) {
                v[j] = acc[i][j] + bj[j];
                x[j] = As[(rbase+i)*64 + c0 + j];
                sqv += v[j]*v[j];
                sqx += x[j]*x[j];
            }
            sqv += __shfl_xor_sync(0xffffffffu, sqv, 1);
            sqv += __shfl_xor_sync(0xffffffffu, sqv, 2);
            sqv += __shfl_xor_sync(0xffffffffu, sqv, 4);
            sqx += __shfl_xor_sync(0xffffffffu, sqx, 1);
            sqx += __shfl_xor_sync(0xffffffffu, sqx, 2);
            sqx += __shfl_xor_sync(0xffffffffu, sqx, 4);
            float itn = 1.0f / fmaxf(sqrtf(sqv), 1e-8f);
            float ixn = 1.0f / fmaxf(sqrtf(sqx), 1e-8f);
            if (gr < rows) {
                float d[8];
#pragma unroll
                for (int j = 0; j < 8; j++) d[j] = v[j]*itn - x[j]*ixn;
                float* dst = &g_diff[(size_t)gr*192 + b*64 + c0];
                *(float4*)&dst[0] = make_float4(d[0],d[1],d[2],d[3]);
                *(float4*)&dst[4] = make_float4(d[4],d[5],d[6],d[7]);
            }
        }
    }
}

// ---------------- degree counting (both directions) ----------------
__global__ void outcount_kernel(const int* __restrict__ ei)
{
    int e = blockIdx.x * blockDim.x + threadIdx.x;
    if (e >= Ee) return;
    int s = ei[e];
    int d = ei[Ee + e];
    atomicAdd(&g_soutdeg[s], 1);
    atomicAdd(&g_indeg[d], 1);
}

// ---------------- dual scan pass A (y=0: src, y=1: dst) ----------------
__global__ void scanA_kernel()
{
    __shared__ int wsum[32];
    const int* in = blockIdx.y ? g_indeg : g_soutdeg;
    int* outp = blockIdx.y ? g_off : g_soff;
    int* bsum = blockIdx.y ? g_bsumD : g_bsumS;
    int tid = threadIdx.x, lane = tid & 31, wid = tid >> 5;
    int idx4 = blockIdx.x * SCAN_TILE + tid * 4;
    int4 v = make_int4(0,0,0,0);
    if (idx4 < Nn) v = *(const int4*)&in[idx4];     // Nn % 4 == 0
    int local = v.x + v.y + v.z + v.w;
    int incl = local;
#pragma unroll
    for (int o = 1; o < 32; o <<= 1) {
        int t = __shfl_up_sync(0xffffffffu, incl, o);
        if (lane >= o) incl += t;
    }
    if (lane == 31) wsum[wid] = incl;
    __syncthreads();
    if (wid == 0) {
        int s = wsum[lane];
        int si = s;
#pragma unroll
        for (int o = 1; o < 32; o <<= 1) {
            int t = __shfl_up_sync(0xffffffffu, si, o);
            if (lane >= o) si += t;
        }
        wsum[lane] = si - s;
        if (lane == 31) bsum[blockIdx.x] = si;
    }
    __syncthreads();
    int excl = wsum[wid] + (incl - local);
    if (idx4 < Nn)
        *(int4*)&outp[idx4] = make_int4(excl, excl+v.x, excl+v.x+v.y, excl+v.x+v.y+v.z);
}

// ---------------- dual scan pass C: add carries ----------------
__global__ void scanC_kernel()
{
    __shared__ int carry_s;
    int* outp = blockIdx.y ? g_off : g_soff;
    const int* bsum = blockIdx.y ? g_bsumD : g_bsumS;
    int tid = threadIdx.x;
    if (tid == 0) {
        int c = 0;
        for (int j = 0; j < (int)blockIdx.x; j++) c += bsum[j];
        carry_s = c;
        if (blockIdx.x == SCAN_BLOCKS - 1)
            outp[Nn] = c + bsum[SCAN_BLOCKS - 1];
    }
    __syncthreads();
    int carry = carry_s;
    if (blockIdx.x == 0 && carry == 0) return;      // nothing to add
    int idx4 = blockIdx.x * SCAN_TILE + tid * 4;
    if (idx4 >= Nn) return;
    int4 o = *(const int4*)&outp[idx4];
    o.x += carry; o.y += carry; o.z += carry; o.w += carry;
    *(int4*)&outp[idx4] = o;
}

// ---------------- src-CSR fill ----------------
__global__ void sfill_kernel(const int* __restrict__ ei)
{
    int e = blockIdx.x * blockDim.x + threadIdx.x;
    if (e >= Ee) return;
    int s = ei[e];
    int d = ei[Ee + e];
    int p = g_soff[s] + atomicAdd(&g_sfill[s], 1);
    g_sdst[p] = d;
}

// ---------------- edge pass: warp per source, masks + direct dst-CSR fill ----------------
__global__ __launch_bounds__(256)
void edge_kernel(const float* __restrict__ feat)
{
    int s = blockIdx.x * 8 + (threadIdx.x >> 5);    // grid exact: 6250*8 = Nn
    int lane = threadIdx.x & 31;
    int g = lane >> 3;
    int q = lane & 7;
    int base = g_soff[s], endp = g_soff[s+1];
    if (base == endp) return;                       // uniform per warp

    const float4* dp = (const float4*)(g_diff + (size_t)s*192);
    float4 a0 = dp[q],      a1 = dp[q + 8];
    float4 b0 = dp[16 + q], b1 = dp[24 + q];
    float4 c0 = dp[32 + q], c1 = dp[40 + q];

    for (int k0 = base; k0 < endp; k0 += 4) {
        int k = k0 + g;
        bool valid = (k < endp);
        int kk = valid ? k : (endp - 1);
        int d = g_sdst[kk];
        const float4* fp = (const float4*)(feat + (size_t)d*64);
        float4 f0 = fp[q], f1 = fp[q + 8];
        float p0 = a0.x*f0.x + a0.y*f0.y + a0.z*f0.z + a0.w*f0.w
                 + a1.x*f1.x + a1.y*f1.y + a1.z*f1.z + a1.w*f1.w;
        float p1 = b0.x*f0.x + b0.y*f0.y + b0.z*f0.z + b0.w*f0.w
                 + b1.x*f1.x + b1.y*f1.y + b1.z*f1.z + b1.w*f1.w;
        float p2 = c0.x*f0.x + c0.y*f0.y + c0.z*f0.z + c0.w*f0.w
                 + c1.x*f1.x + c1.y*f1.y + c1.z*f1.z + c1.w*f1.w;
#pragma unroll
        for (int o = 4; o; o >>= 1) {
            p0 += __shfl_xor_sync(0xffffffffu, p0, o);
            p1 += __shfl_xor_sync(0xffffffffu, p1, o);
            p2 += __shfl_xor_sync(0xffffffffu, p2, o);
        }
        if (q == 0 && valid) {
            unsigned m = 0; int pk = 0;
            if (p0 > 0.f) { m |= 1u; pk += 1; }
            if (p1 > 0.f) { m |= 2u; pk += 1 << 10; }
            if (p2 > 0.f) { m |= 4u; pk += 1 << 20; }
            int pos = g_off[d] + atomicAdd(&g_fill[d], 1);
            g_eid[pos] = s | ((int)m << 16);
            if (pk) atomicAdd(&g_cnt3[d], pk);
        }
    }
}

// ---------------- GCN layer; FUSE=1 adds logits+argmax, writes only replica-0 out ----------------
template<int FUSE>
__global__ __launch_bounds__(256)
void gcn_layer(const float* __restrict__ XW,
               const float* __restrict__ XWfull,
               const float* __restrict__ bias,
               float* __restrict__ out,
               const float* __restrict__ LW,
               const float* __restrict__ Lb)
{
    __shared__ float Wsm[FUSE ? 64*68 : 1];
    __shared__ float bs[FUSE ? 64 : 1];
    __shared__ float rowsm[FUSE ? 8 : 1][4][68];
    int tid = threadIdx.x;
    if (FUSE) {
        for (int i = tid; i < 4096; i += 256) {
            int k = i >> 6, j = i & 63;
            Wsm[k*68 + j] = LW[i];
        }
        if (tid < 64) bs[tid] = Lb[tid];
        __syncthreads();
    }

    int wid = tid >> 5;
    int i = blockIdx.x * 8 + wid;                  // node (grid exact)
    int lane = tid & 31;
    int h = lane >> 4;
    int q = lane & 15;
    float di0 = g_dinv[i];
    float di1 = g_dinv[Nn + i];
    float di2 = g_dinv[2*Nn + i];
    float di3 = g_dinv[3*Nn + i];
    float4 A0 = make_float4(0,0,0,0), A1 = A0, A2 = A0, A3 = A0;
    int beg = g_off[i], end = g_off[i+1];

#define EDGE(kk) { \
        int p = g_eid[kk]; \
        int s = p & 0xFFFF; \
        unsigned m = (unsigned)p >> 16; \
        float ad = g_dinv[s]; \
        float4 r = ((const float4*)(XW + (size_t)s*Ff))[q]; \
        float c0 = ad * di0; \
        A0.x += r.x*c0; A0.y += r.y*c0; A0.z += r.z*c0; A0.w += r.w*c0; \
        if (m & 1u) { float c = ad*di1; A1.x += r.x*c; A1.y += r.y*c; A1.z += r.z*c; A1.w += r.w*c; } \
        if (m & 2u) { float c = ad*di2; A2.x += r.x*c; A2.y += r.y*c; A2.z += r.z*c; A2.w += r.w*c; } \
        if (m & 4u) { float c = ad*di3; A3.x += r.x*c; A3.y += r.y*c; A3.z += r.z*c; A3.w += r.w*c; } }

    int k = beg + h;
    for (; k + 2 < end; k += 4) { EDGE(k); EDGE(k + 2); }
    if (k < end) EDGE(k);
#undef EDGE

#define COMB(A) \
    A.x += __shfl_xor_sync(0xffffffffu, A.x, 16); \
    A.y += __shfl_xor_sync(0xffffffffu, A.y, 16); \
    A.z += __shfl_xor_sync(0xffffffffu, A.z, 16); \
    A.w += __shfl_xor_sync(0xffffffffu, A.w, 16);
    COMB(A0) COMB(A1) COMB(A2) COMB(A3)
#undef COMB

    float4 s0 = ((const float4*)(XW + (size_t)i*Ff))[q];
    float4 bv = ((const float4*)bias)[q];

    float4 oA, oB;
    if (h == 0) {
        float c = di0*di0;
        oA.x = A0.x + s0.x*c + bv.x; oA.y = A0.y + s0.y*c + bv.y;
        oA.z = A0.z + s0.z*c + bv.z; oA.w = A0.w + s0.w*c + bv.w;
        float car = di0 * di1, cs = di1 * di1;
        float4 sr = FUSE ? ((const float4*)(XWfull + ((size_t)Nn + i)*Ff))[q] : s0;
        oB.x = A1.x + s0.x*car + sr.x*cs + bv.x; oB.y = A1.y + s0.y*car + sr.y*cs + bv.y;
        oB.z = A1.z + s0.z*car + sr.z*cs + bv.z; oB.w = A1.w + s0.w*car + sr.w*cs + bv.w;
    } else {
        float car = di0 * di2, cs = di2 * di2;
        float4 sr = FUSE ? ((const float4*)(XWfull + ((size_t)2*Nn + i)*Ff))[q] : s0;
        oA.x = A2.x + s0.x*car + sr.x*cs + bv.x; oA.y = A2.y + s0.y*car + sr.y*cs + bv.y;
        oA.z = A2.z + s0.z*car + sr.z*cs + bv.z; oA.w = A2.w + s0.w*car + sr.w*cs + bv.w;
        car = di0 * di3; cs = di3 * di3;
        sr = FUSE ? ((const float4*)(XWfull + ((size_t)3*Nn + i)*Ff))[q] : s0;
        oB.x = A3.x + s0.x*car + sr.x*cs + bv.x; oB.y = A3.y + s0.y*car + sr.y*cs + bv.y;
        oB.z = A3.z + s0.z*car + sr.z*cs + bv.z; oB.w = A3.w + s0.w*car + sr.w*cs + bv.w;
    }

    if (!FUSE) {
        float4 a = oA, b2 = oB;
        a.x=fmaxf(a.x,0.f); a.y=fmaxf(a.y,0.f); a.z=fmaxf(a.z,0.f); a.w=fmaxf(a.w,0.f);
        b2.x=fmaxf(b2.x,0.f); b2.y=fmaxf(b2.y,0.f); b2.z=fmaxf(b2.z,0.f); b2.w=fmaxf(b2.w,0.f);
        if (h == 0) {
            ((float4*)(out + (size_t)i*Ff))[q] = a;
            ((float4*)(out + ((size_t)Nn + i)*Ff))[q] = b2;
        } else {
            ((float4*)(out + ((size_t)2*Nn + i)*Ff))[q] = a;
            ((float4*)(out + ((size_t)3*Nn + i)*Ff))[q] = b2;
        }
    } else {
        if (h == 0) ((float4*)(out + (size_t)i*Ff))[q] = oA;
        *(float4*)&rowsm[wid][2*h + 0][4*q] = oA;
        *(float4*)&rowsm[wid][2*h + 1][4*q] = oB;
        __syncwarp();

        float a0[4], a1[4];
#pragma unroll
        for (int j = 0; j < 4; j++) { a0[j] = bs[4*q + j]; a1[j] = bs[4*q + j]; }
        const float* r0 = rowsm[wid][2*h + 0];
        const float* r1 = rowsm[wid][2*h + 1];
#pragma unroll 8
        for (int kk = 0; kk < 64; kk++) {
            float h0 = fmaxf(r0[kk], 0.f);
            float h1 = fmaxf(r1[kk], 0.f);
            float4 w = *(const float4*)&Wsm[kk*68 + 4*q];
            a0[0] += h0*w.x; a0[1] += h0*w.y; a0[2] += h0*w.z; a0[3] += h0*w.w;
            a1[0] += h1*w.x; a1[1] += h1*w.y; a1[2] += h1*w.z; a1[3] += h1*w.w;
        }
        float bv0 = a0[0]; int bi0 = 4*q;
        float bv1 = a1[0]; int bi1 = 4*q;
#pragma unroll
        for (int j = 1; j < 4; j++) {
            if (a0[j] > bv0) { bv0 = a0[j]; bi0 = 4*q + j; }
            if (a1[j] > bv1) { bv1 = a1[j]; bi1 = 4*q + j; }
        }
#pragma unroll
        for (int o = 1; o < 16; o <<= 1) {
            float ov0 = __shfl_xor_sync(0xffffffffu, bv0, o);
            int   oi0 = __shfl_xor_sync(0xffffffffu, bi0, o);
            float ov1 = __shfl_xor_sync(0xffffffffu, bv1, o);
            int   oi1 = __shfl_xor_sync(0xffffffffu, bi1, o);
            if (ov0 > bv0 || (ov0 == bv0 && oi0 < bi0)) { bv0 = ov0; bi0 = oi0; }
            if (ov1 > bv1 || (ov1 == bv1 && oi1 < bi1)) { bv1 = ov1; bi1 = oi1; }
        }
        if (q == 0) {
            g_cls[(size_t)(2*h + 0)*Nn + i] = bi0;
            g_cls[(size_t)(2*h + 1)*Nn + i] = bi1;
        }
    }
}

// ---------------- class aggregation: hyper + softmax column sums ----------------
__global__ void classagg_kernel()
{
    __shared__ float hy[NSs][Ff];
    __shared__ float cs[NSs];
    int tid = threadIdx.x;
    for (int i = tid; i < NSs*Ff; i += 256) (&hy[0][0])[i] = 0.0f;
    if (tid < NSs) cs[tid] = 0.0f;
    __syncthreads();
    int wid = tid >> 5, lane = tid & 31;
    for (int n = blockIdx.x * 8 + wid; n < Nn; n += gridDim.x * 8) {
        int c0 = g_cls[n], c1 = g_cls[Nn + n], c2 = g_cls[2*Nn + n], c3 = g_cls[3*Nn + n];
        float2 x = ((const float2*)(g_x2 + (size_t)n*64))[lane];
#define PROC(c, cnt) { \
        atomicAdd(&hy[(c)][2*lane], x.x); atomicAdd(&hy[(c)][2*lane+1], x.y); \
        if (lane == 0) atomicAdd(&cs[(c)], expf((float)(cnt)) - 1.0f); }
        { int cnt = 1 + (c1==c0) + (c2==c0) + (c3==c0); PROC(c0, cnt); }
        if (c1 != c0)                         { int cnt = 1 + (c2==c1) + (c3==c1); PROC(c1, cnt); }
        if (c2 != c0 && c2 != c1)             { int cnt = 1 + (c3==c2);            PROC(c2, cnt); }
        if (c3 != c0 && c3 != c1 && c3 != c2) {                                    PROC(c3, 1);   }
#undef PROC
    }
    __syncthreads();
    for (int i = tid; i < NSs*Ff; i += 256) atomicAdd(&g_hyper[i], (&hy[0][0])[i]);
    if (tid < NSs) atomicAdd(&g_colsum[tid], cs[tid]);
}

// ---------------- fused outputs: H_soft + hyper copy + dots ----------------
__global__ __launch_bounds__(256)
void outputs_kernel(const float* __restrict__ feat,
                    float* __restrict__ outHs, float* __restrict__ outHy,
                    float* __restrict__ outD)
{
    __shared__ __align__(16) float hyT[64][68];
    __shared__ float inv[NSs];
    __shared__ __align__(16) float frow[8][64];
    int tid = threadIdx.x;
    for (int i = tid; i < 4096; i += 256) hyT[i >> 6][i & 63] = g_hyper[i];
    if (tid < NSs) inv[tid] = 1.0f / g_colsum[tid];
    if (blockIdx.x == 0)
        for (int i = tid; i < 4096; i += 256) outHy[i] = g_hyper[i];
    __syncthreads();

    int wid = tid >> 5, lane = tid & 31;
    int n = blockIdx.x * 8 + wid;
    int c0 = g_cls[n], c1 = g_cls[Nn + n], c2 = g_cls[2*Nn + n], c3 = g_cls[3*Nn + n];

    float v0 = inv[2*lane], v1 = inv[2*lane + 1];
#define APPLY(c, cnt) { int cc = (c); if ((cc >> 1) == lane) { \
        float ev = expf((float)(cnt)) * inv[cc]; if (cc & 1) v1 = ev; else v0 = ev; } }
    { int cnt = 1 + (c1==c0) + (c2==c0) + (c3==c0); APPLY(c0, cnt); }
    if (c1 != c0)                         { int cnt = 1 + (c2==c1) + (c3==c1); APPLY(c1, cnt); }
    if (c2 != c0 && c2 != c1)             { int cnt = 1 + (c3==c2);            APPLY(c2, cnt); }
    if (c3 != c0 && c3 != c1 && c3 != c2) {                                    APPLY(c3, 1);   }
#undef APPLY
    ((float2*)(outHs + (size_t)n*64))[lane] = make_float2(v0, v1);

    float2 v = ((const float2*)(feat + (size_t)n*64))[lane];
    frow[wid][2*lane] = v.x; frow[wid][2*lane+1] = v.y;
    __syncwarp();
    float l0 = 0.f, l1 = 0.f;
#pragma unroll
    for (int k = 0; k < 64; k += 4) {
        float4 h4 = *(const float4*)&frow[wid][k];
        float4 wa = *(const float4*)&hyT[lane][k];
        float4 wb = *(const float4*)&hyT[lane + 32][k];
        l0 += h4.x*wa.x + h4.y*wa.y + h4.z*wa.z + h4.w*wa.w;
        l1 += h4.x*wb.x + h4.y*wb.y + h4.z*wb.z + h4.w*wb.w;
    }
    const float SCALE = 0.125f;
    l0 *= SCALE; l1 *= SCALE;
#pragma unroll
    for (int rep = 0; rep < 4; rep++) {
        float* base = outD + ((size_t)rep*Nn + n)*64;
        base[lane] = l0;
        base[lane + 32] = l1;
    }
}

// ---------------- launcher ----------------
extern "C" void kernel_launch(void* const* d_in, const int* in_sizes, int n_in,
                              void* d_out, int out_size)
{
    (void)in_sizes; (void)n_in; (void)out_size;
    const int*   ei   = (const int*)d_in[0];
    const float* feat = (const float*)d_in[1];
    const float* Wlin = (const float*)d_in[2];
    const float* blin = (const float*)d_in[3];
    const float* g0W  = (const float*)d_in[4];
    const float* g0b  = (const float*)d_in[5];
    const float* g1W  = (const float*)d_in[6];
    const float* g1b  = (const float*)d_in[7];
    const float* l1W  = (const float*)d_in[8];
    const float* l1b  = (const float*)d_in[9];

    float* out   = (float*)d_out;
    float* outHs = out;
    float* outHy = out + (size_t)Nn*NSs;
    float* outD  = out + (size_t)Nn*NSs + (size_t)NSs*Ff;

    float *p_xw0, *p_h1, *p_xw1, *p_x2;
    cudaGetSymbolAddress((void**)&p_xw0, g_xw0);
    cudaGetSymbolAddress((void**)&p_h1,  g_h1);
    cudaGetSymbolAddress((void**)&p_xw1, g_xw1);
    cudaGetSymbolAddress((void**)&p_x2,  g_x2);

    const int GB_N    = (Nn + 127) / 128;     // 391
    const int GB_NTOT = (NTOT + 127) / 128;   // 1563

    // per-replica linear transforms -> diff rows (+ fused global init)
    gemm_rb<<<dim3(GB_N, 3), 128>>>(feat, Wlin, blin, nullptr, Nn, 0, 1);

    outcount_kernel<<<(Ee + 255)/256, 256>>>(ei);
    scanA_kernel<<<dim3(SCAN_BLOCKS, 2), 1024>>>();
    scanC_kernel<<<dim3(SCAN_BLOCKS, 2), 1024>>>();
    sfill_kernel<<<(Ee + 255)/256, 256>>>(ei);
    edge_kernel<<<Nn/8, 256>>>(feat);

    // layer 0 (+ fused dinv)
    gemm_rb<<<dim3(GB_N, 1), 128>>>(feat, g0W, nullptr, p_xw0, Nn, 1, 2);
    gcn_layer<0><<<Nn/8, 256>>>(p_xw0, p_xw0, g0b, p_h1, nullptr, nullptr);

    // layer 1 (+ fused logits/argmax)
    gemm_rb<<<dim3(GB_NTOT, 1), 128>>>(p_h1, g1W, nullptr, p_xw1, NTOT, 0, 0);
    gcn_layer<1><<<Nn/8, 256>>>(p_xw1, p_xw1, g1b, p_x2, l1W, l1b);

    classagg_kernel<<<128, 256>>>();
    outputs_kernel<<<Nn/8, 256>>>(feat, outHs, outHy, outD);
}

// round 10
// speedup vs baseline: 1.0224x; 1.0224x over previous
#include <cuda_runtime.h>
#include <math.h>

#define Nn 50000
#define Ee 800000
#define Ff 64
#define Tt 3
#define NSs 64
#define NTOT (4*Nn)
#define SCAN_TILE 4096
#define SCAN_BLOCKS ((Nn + SCAN_TILE - 1) / SCAN_TILE)   // 13

// ---------------- scratch (device globals; no allocation allowed) ----------------
__device__ __align__(16) float g_diff[Nn*192];   // per node: 3 normalized-difference rows
__device__ int g_indeg[Nn];
__device__ int g_cnt3[Nn];                        // c1|c2<<10|c3<<20
__device__ int g_fill[Nn];
__device__ int g_off[Nn+1];
__device__ int g_eid[Ee];                         // dst-CSR: src, later src | (mask<<16)
__device__ int g_bsum[SCAN_BLOCKS];
__device__ float g_dinv[4*Nn];
__device__ __align__(16) float g_xw0[Nn*Ff];      // pre-scaled by dinv0
__device__ __align__(16) float g_h1[NTOT*Ff];
__device__ __align__(16) float g_xw1[NTOT*Ff];    // rows < Nn pre-scaled by dinv0
__device__ __align__(16) float g_x2[Nn*Ff];       // replica-0 rows only
__device__ int g_cls[NTOT];
__device__ __align__(16) float g_hyper[NSs*Ff];
__device__ float g_colsum[NSs];

// ---------------- register-blocked GEMM: out = (relu?)X @ W (+bias), K=N=64 ----------------
// mode 1: diff rows + global init.
// mode 2: prologue computes dinv[Nn..4Nn) from cnt3; epilogue scales rows<Nn by dinv0.
// mode 3: epilogue scales rows<Nn by dinv0.
__global__ __launch_bounds__(128)
void gemm_rb(const float* __restrict__ X, const float* __restrict__ W,
             const float* __restrict__ bias, float* __restrict__ out,
             int rows, int relu_in, int mode)
{
    __shared__ float As[128*64];   // 32KB
    __shared__ float Bs[64*64];    // 16KB
    const int tid = threadIdx.x;
    const int tx = tid & 7;
    const int ty = tid >> 3;
    const int b  = blockIdx.y;
    const int row0 = blockIdx.x * 128;

    if (mode == 1 && b == 0) {
        int gi = blockIdx.x * 128 + tid;
        if (gi < Nn) { g_indeg[gi] = 0; g_fill[gi] = 0; g_cnt3[gi] = 0; }
        if (blockIdx.x == 0) {
            for (int i = tid; i < NSs*Ff; i += 128) g_hyper[i] = 0.0f;
            if (tid < NSs) g_colsum[tid] = (float)Nn;
        }
    }
    if (mode == 2 && b == 0) {
        int gi = blockIdx.x * 128 + tid;
        if (gi < Nn) {
            int pk = g_cnt3[gi];
            g_dinv[Nn + gi]   = rsqrtf((float)(pk & 1023) + 2.0f);
            g_dinv[2*Nn + gi] = rsqrtf((float)((pk >> 10) & 1023) + 2.0f);
            g_dinv[3*Nn + gi] = rsqrtf((float)((pk >> 20) & 1023) + 2.0f);
        }
    }

    const float* Wb = W + (size_t)b * 4096;

#pragma unroll
    for (int it = 0; it < 16; it++) {
        int idx = tid + it * 128;
        int r = idx >> 4, c4 = (idx & 15) << 2;
        int gr = row0 + r;
        float4 v = make_float4(0.f, 0.f, 0.f, 0.f);
        if (gr < rows) v = *(const float4*)&X[(size_t)gr*64 + c4];
        if (relu_in) { v.x = fmaxf(v.x,0.f); v.y = fmaxf(v.y,0.f); v.z = fmaxf(v.z,0.f); v.w = fmaxf(v.w,0.f); }
        *(float4*)&As[r*64 + c4] = v;
    }
#pragma unroll
    for (int it = 0; it < 8; it++) {
        int idx = tid + it * 128;
        int k = idx >> 4, c4 = (idx & 15) << 2;
        *(float4*)&Bs[k*64 + c4] = *(const float4*)&Wb[k*64 + c4];
    }
    __syncthreads();

    float acc[8][8];
#pragma unroll
    for (int i = 0; i < 8; i++)
#pragma unroll
        for (int j = 0; j < 8; j++) acc[i][j] = 0.f;

    const int rbase = ty * 8;
    const int c0 = tx * 8;
#pragma unroll
    for (int k0 = 0; k0 < 64; k0 += 4) {
        float4 a[8];
#pragma unroll
        for (int i = 0; i < 8; i++) a[i] = *(const float4*)&As[(rbase+i)*64 + k0];
#pragma unroll
        for (int kk = 0; kk < 4; kk++) {
            float4 b0 = *(const float4*)&Bs[(k0+kk)*64 + c0];
            float4 b1 = *(const float4*)&Bs[(k0+kk)*64 + c0 + 4];
            float bb[8] = {b0.x,b0.y,b0.z,b0.w,b1.x,b1.y,b1.z,b1.w};
#pragma unroll
            for (int i = 0; i < 8; i++) {
                float av = (kk==0) ? a[i].x : (kk==1) ? a[i].y : (kk==2) ? a[i].z : a[i].w;
#pragma unroll
                for (int j = 0; j < 8; j++) acc[i][j] += av * bb[j];
            }
        }
    }

    float bj[8];
#pragma unroll
    for (int j = 0; j < 8; j++) bj[j] = bias ? bias[(size_t)b*64 + c0 + j] : 0.f;

    if (mode != 1) {
        float* outb = out + (size_t)b * rows * 64;
#pragma unroll
        for (int i = 0; i < 8; i++) {
            int gr = row0 + rbase + i;
            if (gr >= rows) continue;
            float scale = 1.0f;
            if (mode >= 2 && gr < Nn) scale = g_dinv[gr];
            float v[8];
#pragma unroll
            for (int j = 0; j < 8; j++) v[j] = (acc[i][j] + bj[j]) * scale;
            *(float4*)&outb[(size_t)gr*64 + c0]     = make_float4(v[0],v[1],v[2],v[3]);
            *(float4*)&outb[(size_t)gr*64 + c0 + 4] = make_float4(v[4],v[5],v[6],v[7]);
        }
    } else {
#pragma unroll
        for (int i = 0; i < 8; i++) {
            int gr = row0 + rbase + i;
            float v[8], x[8];
            float sqv = 0.f, sqx = 0.f;
#pragma unroll
            for (int j = 0; j < 8; j++) {
                v[j] = acc[i][j] + bj[j];
                x[j] = As[(rbase+i)*64 + c0 + j];
                sqv += v[j]*v[j];
                sqx += x[j]*x[j];
            }
            sqv += __shfl_xor_sync(0xffffffffu, sqv, 1);
            sqv += __shfl_xor_sync(0xffffffffu, sqv, 2);
            sqv += __shfl_xor_sync(0xffffffffu, sqv, 4);
            sqx += __shfl_xor_sync(0xffffffffu, sqx, 1);
            sqx += __shfl_xor_sync(0xffffffffu, sqx, 2);
            sqx += __shfl_xor_sync(0xffffffffu, sqx, 4);
            float itn = 1.0f / fmaxf(sqrtf(sqv), 1e-8f);
            float ixn = 1.0f / fmaxf(sqrtf(sqx), 1e-8f);
            if (gr < rows) {
                float d[8];
#pragma unroll
                for (int j = 0; j < 8; j++) d[j] = v[j]*itn - x[j]*ixn;
                float* dst = &g_diff[(size_t)gr*192 + b*64 + c0];
                *(float4*)&dst[0] = make_float4(d[0],d[1],d[2],d[3]);
                *(float4*)&dst[4] = make_float4(d[4],d[5],d[6],d[7]);
            }
        }
    }
}

// ---------------- in-degree counting ----------------
__global__ void outcount_kernel(const int* __restrict__ ei)
{
    int e = blockIdx.x * blockDim.x + threadIdx.x;
    if (e >= Ee) return;
    atomicAdd(&g_indeg[ei[Ee + e]], 1);
}

// ---------------- scan pass A ----------------
__global__ void scanA_kernel()
{
    __shared__ int wsum[32];
    int tid = threadIdx.x, lane = tid & 31, wid = tid >> 5;
    int idx4 = blockIdx.x * SCAN_TILE + tid * 4;
    int4 v = make_int4(0,0,0,0);
    if (idx4 < Nn) v = *(const int4*)&g_indeg[idx4];    // Nn % 4 == 0
    int local = v.x + v.y + v.z + v.w;
    int incl = local;
#pragma unroll
    for (int o = 1; o < 32; o <<= 1) {
        int t = __shfl_up_sync(0xffffffffu, incl, o);
        if (lane >= o) incl += t;
    }
    if (lane == 31) wsum[wid] = incl;
    __syncthreads();
    if (wid == 0) {
        int s = wsum[lane];
        int si = s;
#pragma unroll
        for (int o = 1; o < 32; o <<= 1) {
            int t = __shfl_up_sync(0xffffffffu, si, o);
            if (lane >= o) si += t;
        }
        wsum[lane] = si - s;
        if (lane == 31) g_bsum[blockIdx.x] = si;
    }
    __syncthreads();
    int excl = wsum[wid] + (incl - local);
    if (idx4 < Nn)
        *(int4*)&g_off[idx4] = make_int4(excl, excl+v.x, excl+v.x+v.y, excl+v.x+v.y+v.z);
}

// ---------------- scan pass C: carries + dinv0 ----------------
__global__ void scanC_kernel()
{
    __shared__ int carry_s;
    int tid = threadIdx.x;
    if (tid == 0) {
        int c = 0;
        for (int j = 0; j < (int)blockIdx.x; j++) c += g_bsum[j];
        carry_s = c;
        if (blockIdx.x == SCAN_BLOCKS - 1)
            g_off[Nn] = c + g_bsum[SCAN_BLOCKS - 1];
    }
    __syncthreads();
    int carry = carry_s;
    int idx4 = blockIdx.x * SCAN_TILE + tid * 4;
    if (idx4 >= Nn) return;
    int4 dg = *(const int4*)&g_indeg[idx4];
    g_dinv[idx4]   = rsqrtf((float)dg.x + 1.0f);
    g_dinv[idx4+1] = rsqrtf((float)dg.y + 1.0f);
    g_dinv[idx4+2] = rsqrtf((float)dg.z + 1.0f);
    g_dinv[idx4+3] = rsqrtf((float)dg.w + 1.0f);
    if (carry) {
        int4 o = *(const int4*)&g_off[idx4];
        o.x += carry; o.y += carry; o.z += carry; o.w += carry;
        *(int4*)&g_off[idx4] = o;
    }
}

// ---------------- dst-CSR fill (raw src ids) ----------------
__global__ void fill_kernel(const int* __restrict__ ei)
{
    int e = blockIdx.x * blockDim.x + threadIdx.x;
    if (e >= Ee) return;
    int s = ei[e];
    int d = ei[Ee + e];
    int p = g_off[d] + atomicAdd(&g_fill[d], 1);
    g_eid[p] = s;
}

// ---------------- mask pass: warp per destination, in-place g_eid update ----------------
__global__ __launch_bounds__(256)
void edgemask_kernel(const float* __restrict__ feat)
{
    int d = blockIdx.x * 8 + (threadIdx.x >> 5);    // grid exact: 6250*8 = Nn
    int lane = threadIdx.x & 31;
    int g = lane >> 3;
    int q = lane & 7;
    int base = g_off[d], endp = g_off[d+1];

    const float4* fp = (const float4*)(feat + (size_t)d*64);
    float4 f0 = fp[q], f1 = fp[q + 8];

    int cnt = 0;                                    // packed c1|c2<<10|c3<<20
    for (int k0 = base; k0 < endp; k0 += 4) {
        int k = k0 + g;
        bool valid = (k < endp);
        int kk = valid ? k : base;
        int s = g_eid[kk] & 0xFFFF;                 // strip mask bits (inactive lanes may
                                                    // re-read an already-rewritten entry)
        const float4* dp = (const float4*)(g_diff + (size_t)s*192);
        float4 a0 = dp[q],      a1 = dp[q + 8];
        float4 b0 = dp[16 + q], b1 = dp[24 + q];
        float4 c0 = dp[32 + q], c1 = dp[40 + q];
        float p0 = a0.x*f0.x + a0.y*f0.y + a0.z*f0.z + a0.w*f0.w
                 + a1.x*f1.x + a1.y*f1.y + a1.z*f1.z + a1.w*f1.w;
        float p1 = b0.x*f0.x + b0.y*f0.y + b0.z*f0.z + b0.w*f0.w
                 + b1.x*f1.x + b1.y*f1.y + b1.z*f1.z + b1.w*f1.w;
        float p2 = c0.x*f0.x + c0.y*f0.y + c0.z*f0.z + c0.w*f0.w
                 + c1.x*f1.x + c1.y*f1.y + c1.z*f1.z + c1.w*f1.w;
#pragma unroll
        for (int o = 4; o; o >>= 1) {
            p0 += __shfl_xor_sync(0xffffffffu, p0, o);
            p1 += __shfl_xor_sync(0xffffffffu, p1, o);
            p2 += __shfl_xor_sync(0xffffffffu, p2, o);
        }
        if (q == 0 && valid) {
            int m = 0, pk = 0;
            if (p0 > 0.f) { m |= 1;  pk += 1; }
            if (p1 > 0.f) { m |= 2;  pk += 1 << 10; }
            if (p2 > 0.f) { m |= 4;  pk += 1 << 20; }
            g_eid[k] = s | (m << 16);
            cnt += pk;
        }
    }
    // combine group leaders (lanes 0,8,16,24)
    cnt += __shfl_xor_sync(0xffffffffu, cnt, 8);
    cnt += __shfl_xor_sync(0xffffffffu, cnt, 16);
    if (lane == 0) g_cnt3[d] = cnt;
}

// ---------------- GCN layer (gather rows pre-scaled by dinv0[src]) ----------------
// FUSE=1 adds logits+argmax, writes only replica-0 out.
template<int FUSE>
__global__ __launch_bounds__(256)
void gcn_layer(const float* __restrict__ XW,       // scaled rows (first Nn)
               const float* __restrict__ XWfull,   // full rows (self terms, layer 1)
               const float* __restrict__ bias,
               float* __restrict__ out,
               const float* __restrict__ LW,
               const float* __restrict__ Lb)
{
    __shared__ float Wsm[FUSE ? 64*68 : 1];
    __shared__ float bs[FUSE ? 64 : 1];
    __shared__ float rowsm[FUSE ? 8 : 1][4][68];
    int tid = threadIdx.x;
    if (FUSE) {
        for (int i = tid; i < 4096; i += 256) {
            int k = i >> 6, j = i & 63;
            Wsm[k*68 + j] = LW[i];
        }
        if (tid < 64) bs[tid] = Lb[tid];
        __syncthreads();
    }

    int wid = tid >> 5;
    int i = blockIdx.x * 8 + wid;                  // node (grid exact)
    int lane = tid & 31;
    int h = lane >> 4;
    int q = lane & 15;
    float di0 = g_dinv[i];
    float di1 = g_dinv[Nn + i];
    float di2 = g_dinv[2*Nn + i];
    float di3 = g_dinv[3*Nn + i];
    float rdi0 = 1.0f / di0;
    float4 A0 = make_float4(0,0,0,0), A1 = A0, A2 = A0, A3 = A0;
    int beg = g_off[i], end = g_off[i+1];

#define EDGE(kk) { \
        int p = g_eid[kk]; \
        int s = p & 0xFFFF; \
        unsigned m = (unsigned)p >> 16; \
        float4 r = ((const float4*)(XW + (size_t)s*Ff))[q]; \
        A0.x += r.x; A0.y += r.y; A0.z += r.z; A0.w += r.w; \
        if (m & 1u) { A1.x += r.x; A1.y += r.y; A1.z += r.z; A1.w += r.w; } \
        if (m & 2u) { A2.x += r.x; A2.y += r.y; A2.z += r.z; A2.w += r.w; } \
        if (m & 4u) { A3.x += r.x; A3.y += r.y; A3.z += r.z; A3.w += r.w; } }

    int k = beg + h;
    for (; k + 2 < end; k += 4) { EDGE(k); EDGE(k + 2); }
    if (k < end) EDGE(k);
#undef EDGE

#define COMB(A) \
    A.x += __shfl_xor_sync(0xffffffffu, A.x, 16); \
    A.y += __shfl_xor_sync(0xffffffffu, A.y, 16); \
    A.z += __shfl_xor_sync(0xffffffffu, A.z, 16); \
    A.w += __shfl_xor_sync(0xffffffffu, A.w, 16);
    COMB(A0) COMB(A1) COMB(A2) COMB(A3)
#undef COMB

    float4 s0 = ((const float4*)(XW + (size_t)i*Ff))[q];   // scaled self row
    float4 bv = ((const float4*)bias)[q];

    float4 oA, oB;
    if (h == 0) {
        oA.x = di0*(A0.x + s0.x) + bv.x; oA.y = di0*(A0.y + s0.y) + bv.y;
        oA.z = di0*(A0.z + s0.z) + bv.z; oA.w = di0*(A0.w + s0.w) + bv.w;
        if (FUSE) {
            float4 sr = ((const float4*)(XWfull + ((size_t)Nn + i)*Ff))[q];
            float cs = di1*di1;
            oB.x = di1*(A1.x + s0.x) + cs*sr.x + bv.x; oB.y = di1*(A1.y + s0.y) + cs*sr.y + bv.y;
            oB.z = di1*(A1.z + s0.z) + cs*sr.z + bv.z; oB.w = di1*(A1.w + s0.w) + cs*sr.w + bv.w;
        } else {
            float c = di1 + di1*di1*rdi0;
            oB.x = di1*A1.x + c*s0.x + bv.x; oB.y = di1*A1.y + c*s0.y + bv.y;
            oB.z = di1*A1.z + c*s0.z + bv.z; oB.w = di1*A1.w + c*s0.w + bv.w;
        }
    } else {
        if (FUSE) {
            float4 sr = ((const float4*)(XWfull + ((size_t)2*Nn + i)*Ff))[q];
            float cs = di2*di2;
            oA.x = di2*(A2.x + s0.x) + cs*sr.x + bv.x; oA.y = di2*(A2.y + s0.y) + cs*sr.y + bv.y;
            oA.z = di2*(A2.z + s0.z) + cs*sr.z + bv.z; oA.w = di2*(A2.w + s0.w) + cs*sr.w + bv.w;
            sr = ((const float4*)(XWfull + ((size_t)3*Nn + i)*Ff))[q];
            cs = di3*di3;
            oB.x = di3*(A3.x + s0.x) + cs*sr.x + bv.x; oB.y = di3*(A3.y + s0.y) + cs*sr.y + bv.y;
            oB.z = di3*(A3.z + s0.z) + cs*sr.z + bv.z; oB.w = di3*(A3.w + s0.w) + cs*sr.w + bv.w;
        } else {
            float c = di2 + di2*di2*rdi0;
            oA.x = di2*A2.x + c*s0.x + bv.x; oA.y = di2*A2.y + c*s0.y + bv.y;
            oA.z = di2*A2.z + c*s0.z + bv.z; oA.w = di2*A2.w + c*s0.w + bv.w;
            c = di3 + di3*di3*rdi0;
            oB.x = di3*A3.x + c*s0.x + bv.x; oB.y = di3*A3.y + c*s0.y + bv.y;
            oB.z = di3*A3.z + c*s0.z + bv.z; oB.w = di3*A3.w + c*s0.w + bv.w;
        }
    }

    if (!FUSE) {
        float4 a = oA, b2 = oB;
        a.x=fmaxf(a.x,0.f); a.y=fmaxf(a.y,0.f); a.z=fmaxf(a.z,0.f); a.w=fmaxf(a.w,0.f);
        b2.x=fmaxf(b2.x,0.f); b2.y=fmaxf(b2.y,0.f); b2.z=fmaxf(b2.z,0.f); b2.w=fmaxf(b2.w,0.f);
        if (h == 0) {
            ((float4*)(out + (size_t)i*Ff))[q] = a;
            ((float4*)(out + ((size_t)Nn + i)*Ff))[q] = b2;
        } else {
            ((float4*)(out + ((size_t)2*Nn + i)*Ff))[q] = a;
            ((float4*)(out + ((size_t)3*Nn + i)*Ff))[q] = b2;
        }
    } else {
        if (h == 0) ((float4*)(out + (size_t)i*Ff))[q] = oA;
        *(float4*)&rowsm[wid][2*h + 0][4*q] = oA;
        *(float4*)&rowsm[wid][2*h + 1][4*q] = oB;
        __syncwarp();

        float a0[4], a1[4];
#pragma unroll
        for (int j = 0; j < 4; j++) { a0[j] = bs[4*q + j]; a1[j] = bs[4*q + j]; }
        const float* r0 = rowsm[wid][2*h + 0];
        const float* r1 = rowsm[wid][2*h + 1];
#pragma unroll 8
        for (int kk = 0; kk < 64; kk++) {
            float h0 = fmaxf(r0[kk], 0.f);
            float h1 = fmaxf(r1[kk], 0.f);
            float4 w = *(const float4*)&Wsm[kk*68 + 4*q];
            a0[0] += h0*w.x; a0[1] += h0*w.y; a0[2] += h0*w.z; a0[3] += h0*w.w;
            a1[0] += h1*w.x; a1[1] += h1*w.y; a1[2] += h1*w.z; a1[3] += h1*w.w;
        }
        float bv0 = a0[0]; int bi0 = 4*q;
        float bv1 = a1[0]; int bi1 = 4*q;
#pragma unroll
        for (int j = 1; j < 4; j++) {
            if (a0[j] > bv0) { bv0 = a0[j]; bi0 = 4*q + j; }
            if (a1[j] > bv1) { bv1 = a1[j]; bi1 = 4*q + j; }
        }
#pragma unroll
        for (int o = 1; o < 16; o <<= 1) {
            float ov0 = __shfl_xor_sync(0xffffffffu, bv0, o);
            int   oi0 = __shfl_xor_sync(0xffffffffu, bi0, o);
            float ov1 = __shfl_xor_sync(0xffffffffu, bv1, o);
            int   oi1 = __shfl_xor_sync(0xffffffffu, bi1, o);
            if (ov0 > bv0 || (ov0 == bv0 && oi0 < bi0)) { bv0 = ov0; bi0 = oi0; }
            if (ov1 > bv1 || (ov1 == bv1 && oi1 < bi1)) { bv1 = ov1; bi1 = oi1; }
        }
        if (q == 0) {
            g_cls[(size_t)(2*h + 0)*Nn + i] = bi0;
            g_cls[(size_t)(2*h + 1)*Nn + i] = bi1;
        }
    }
}

// ---------------- class aggregation: hyper + softmax column sums ----------------
__global__ void classagg_kernel()
{
    __shared__ float hy[NSs][Ff];
    __shared__ float cs[NSs];
    int tid = threadIdx.x;
    for (int i = tid; i < NSs*Ff; i += 256) (&hy[0][0])[i] = 0.0f;
    if (tid < NSs) cs[tid] = 0.0f;
    __syncthreads();
    int wid = tid >> 5, lane = tid & 31;
    for (int n = blockIdx.x * 8 + wid; n < Nn; n += gridDim.x * 8) {
        int c0 = g_cls[n], c1 = g_cls[Nn + n], c2 = g_cls[2*Nn + n], c3 = g_cls[3*Nn + n];
        float2 x = ((const float2*)(g_x2 + (size_t)n*64))[lane];
#define PROC(c, cnt) { \
        atomicAdd(&hy[(c)][2*lane], x.x); atomicAdd(&hy[(c)][2*lane+1], x.y); \
        if (lane == 0) atomicAdd(&cs[(c)], expf((float)(cnt)) - 1.0f); }
        { int cnt = 1 + (c1==c0) + (c2==c0) + (c3==c0); PROC(c0, cnt); }
        if (c1 != c0)                         { int cnt = 1 + (c2==c1) + (c3==c1); PROC(c1, cnt); }
        if (c2 != c0 && c2 != c1)             { int cnt = 1 + (c3==c2);            PROC(c2, cnt); }
        if (c3 != c0 && c3 != c1 && c3 != c2) {                                    PROC(c3, 1);   }
#undef PROC
    }
    __syncthreads();
    for (int i = tid; i < NSs*Ff; i += 256) atomicAdd(&g_hyper[i], (&hy[0][0])[i]);
    if (tid < NSs) atomicAdd(&g_colsum[tid], cs[tid]);
}

// ---------------- fused outputs: H_soft + hyper copy + dots ----------------
__global__ __launch_bounds__(256)
void outputs_kernel(const float* __restrict__ feat,
                    float* __restrict__ outHs, float* __restrict__ outHy,
                    float* __restrict__ outD)
{
    __shared__ __align__(16) float hyT[64][68];
    __shared__ float inv[NSs];
    __shared__ __align__(16) float frow[8][64];
    int tid = threadIdx.x;
    for (int i = tid; i < 4096; i += 256) hyT[i >> 6][i & 63] = g_hyper[i];
    if (tid < NSs) inv[tid] = 1.0f / g_colsum[tid];
    if (blockIdx.x == 0)
        for (int i = tid; i < 4096; i += 256) outHy[i] = g_hyper[i];
    __syncthreads();

    int wid = tid >> 5, lane = tid & 31;
    int n = blockIdx.x * 8 + wid;
    int c0 = g_cls[n], c1 = g_cls[Nn + n], c2 = g_cls[2*Nn + n], c3 = g_cls[3*Nn + n];

    float v0 = inv[2*lane], v1 = inv[2*lane + 1];
#define APPLY(c, cnt) { int cc = (c); if ((cc >> 1) == lane) { \
        float ev = expf((float)(cnt)) * inv[cc]; if (cc & 1) v1 = ev; else v0 = ev; } }
    { int cnt = 1 + (c1==c0) + (c2==c0) + (c3==c0); APPLY(c0, cnt); }
    if (c1 != c0)                         { int cnt = 1 + (c2==c1) + (c3==c1); APPLY(c1, cnt); }
    if (c2 != c0 && c2 != c1)             { int cnt = 1 + (c3==c2);            APPLY(c2, cnt); }
    if (c3 != c0 && c3 != c1 && c3 != c2) {                                    APPLY(c3, 1);   }
#undef APPLY
    ((float2*)(outHs + (size_t)n*64))[lane] = make_float2(v0, v1);

    float2 v = ((const float2*)(feat + (size_t)n*64))[lane];
    frow[wid][2*lane] = v.x; frow[wid][2*lane+1] = v.y;
    __syncwarp();
    float l0 = 0.f, l1 = 0.f;
#pragma unroll
    for (int k = 0; k < 64; k += 4) {
        float4 h4 = *(const float4*)&frow[wid][k];
        float4 wa = *(const float4*)&hyT[lane][k];
        float4 wb = *(const float4*)&hyT[lane + 32][k];
        l0 += h4.x*wa.x + h4.y*wa.y + h4.z*wa.z + h4.w*wa.w;
        l1 += h4.x*wb.x + h4.y*wb.y + h4.z*wb.z + h4.w*wb.w;
    }
    const float SCALE = 0.125f;
    l0 *= SCALE; l1 *= SCALE;
#pragma unroll
    for (int rep = 0; rep < 4; rep++) {
        float* base = outD + ((size_t)rep*Nn + n)*64;
        base[lane] = l0;
        base[lane + 32] = l1;
    }
}

// ---------------- launcher ----------------
extern "C" void kernel_launch(void* const* d_in, const int* in_sizes, int n_in,
                              void* d_out, int out_size)
{
    (void)in_sizes; (void)n_in; (void)out_size;
    const int*   ei   = (const int*)d_in[0];
    const float* feat = (const float*)d_in[1];
    const float* Wlin = (const float*)d_in[2];
    const float* blin = (const float*)d_in[3];
    const float* g0W  = (const float*)d_in[4];
    const float* g0b  = (const float*)d_in[5];
    const float* g1W  = (const float*)d_in[6];
    const float* g1b  = (const float*)d_in[7];
    const float* l1W  = (const float*)d_in[8];
    const float* l1b  = (const float*)d_in[9];

    float* out   = (float*)d_out;
    float* outHs = out;
    float* outHy = out + (size_t)Nn*NSs;
    float* outD  = out + (size_t)Nn*NSs + (size_t)NSs*Ff;

    float *p_xw0, *p_h1, *p_xw1, *p_x2;
    cudaGetSymbolAddress((void**)&p_xw0, g_xw0);
    cudaGetSymbolAddress((void**)&p_h1,  g_h1);
    cudaGetSymbolAddress((void**)&p_xw1, g_xw1);
    cudaGetSymbolAddress((void**)&p_x2,  g_x2);

    const int GB_N    = (Nn + 127) / 128;     // 391
    const int GB_NTOT = (NTOT + 127) / 128;   // 1563

    // per-replica linear transforms -> diff rows (+ fused global init)
    gemm_rb<<<dim3(GB_N, 3), 128>>>(feat, Wlin, blin, nullptr, Nn, 0, 1);

    outcount_kernel<<<(Ee + 255)/256, 256>>>(ei);
    scanA_kernel<<<SCAN_BLOCKS, 1024>>>();
    scanC_kernel<<<SCAN_BLOCKS, 1024>>>();
    fill_kernel<<<(Ee + 255)/256, 256>>>(ei);
    edgemask_kernel<<<Nn/8, 256>>>(feat);

    // layer 0 (+ fused dinv1-3, output rows pre-scaled by dinv0)
    gemm_rb<<<dim3(GB_N, 1), 128>>>(feat, g0W, nullptr, p_xw0, Nn, 1, 2);
    gcn_layer<0><<<Nn/8, 256>>>(p_xw0, p_xw0, g0b, p_h1, nullptr, nullptr);

    // layer 1 (+ fused logits/argmax; rows<Nn pre-scaled)
    gemm_rb<<<dim3(GB_NTOT, 1), 128>>>(p_h1, g1W, nullptr, p_xw1, NTOT, 0, 3);
    gcn_layer<1><<<Nn/8, 256>>>(p_xw1, p_xw1, g1b, p_x2, l1W, l1b);

    classagg_kernel<<<128, 256>>>();
    outputs_kernel<<<Nn/8, 256>>>(feat, outHs, outHy, outD);
}